// round 6
// baseline (speedup 1.0000x reference)
#include <cuda_runtime.h>
#include <cstdint>
#include <cstddef>

// CapsuleLayer dynamic routing — j-distributed mapping, W-in-registers.
// B=64, IN_CAPS=2048, IN_DIM=8, OUT_CAPS=32, OUT_DIM=16, 3 routing iters.
// Linearity trick: iter2 logits = u.(v0+v1) -> no b_ij matrix needed.

#define NB   64
#define ICAP 2048
#define OC   32
#define OD   16
#define IPER 16
#define GX   (ICAP / IPER)   // 128
#define BC   32              // batches per CTA
#define BLC  16              // batch rows per register chunk (2 chunks)

typedef unsigned long long ull;

__device__ float g_s[NB * OC * OD];   // [b][o][j] accumulators (zeroed by squash)
__device__ float g_v[NB * OC * OD];   // [b][o][j]; iter2 reads v0+v1 here

// ---- f32x2 helpers -------------------------------------------------------
__device__ __forceinline__ ull ffma2(ull a, ull b, ull c) {
    ull d;
    asm("fma.rn.f32x2 %0, %1, %2, %3;" : "=l"(d) : "l"(a), "l"(b), "l"(c));
    return d;
}
__device__ __forceinline__ ull fdup(float x) {
    ull d;
    asm("mov.b64 %0, {%1, %1};" : "=l"(d) : "f"(x));
    return d;
}
__device__ __forceinline__ ull fpk(float lo, float hi) {
    ull d;
    asm("mov.b64 %0, {%1, %2};" : "=l"(d) : "f"(lo), "f"(hi));
    return d;
}
__device__ __forceinline__ float flo(ull v) { return __uint_as_float((unsigned)v); }
__device__ __forceinline__ float fhi(ull v) { return __uint_as_float((unsigned)(v >> 32)); }

__device__ __forceinline__ void red2(float* p, float a, float b) {
    asm volatile("red.global.add.v2.f32 [%0], {%1, %2};"
                 :: "l"(p), "f"(a), "f"(b) : "memory");
}

// SMEM layout:
//   vsh : [BC][256] ull  = 65536 B   (v[b][o][jp] pairs; index within b == t)
//   xsh : [BC][IPER][8] f = 16384 B
//   esh : [2][BLC][32] f  =  4096 B  (double-buffered exp values)
//   ssum: [2][BLC] f      =   128 B  (double-buffered exp-sums)
#define VSH_ULLS (BC * 256)
#define XSH_F    (BC * IPER * 8)
#define SMEM_BYTES (VSH_ULLS * 8 + XSH_F * 4 + 2 * BLC * 32 * 4 + 2 * BLC * 4)

template <int ITER>
__global__ __launch_bounds__(256, 2)
void caps_pass(const float* __restrict__ xg, const float* __restrict__ Wg) {
    extern __shared__ ull smem_u[];
    ull*   vsh  = smem_u;
    float* xsh  = (float*)(smem_u + VSH_ULLS);
    float* esh  = xsh + XSH_F;
    float* ssum = esh + 2 * BLC * 32;

    const int t    = threadIdx.x;
    const int lane = t & 31;
    const int o    = t >> 3;       // output capsule
    const int jp   = t & 7;        // j-pair: j = {2jp, 2jp+1}
    const int b_base = blockIdx.y * BC;
    const int i0     = blockIdx.x * IPER;

    // Stage x: per bl row, IPER*8 = 128 contiguous floats
    {
        const int bl = t >> 3, c8 = t & 7;
        const float4* src = (const float4*)(xg + (size_t)(b_base + bl) * (ICAP * 8) + i0 * 8);
        float4* dst = (float4*)(xsh + bl * (IPER * 8));
        #pragma unroll
        for (int c = 0; c < 4; ++c) dst[c8 * 4 + c] = src[c8 * 4 + c];
    }
    if (ITER >= 1) {
        const ull* vg = ((const ull*)g_v) + (size_t)b_base * 256;
        #pragma unroll
        for (int k = 0; k < 32; ++k) vsh[t + k * 256] = vg[t + k * 256];
        if (t < 2 * BLC) ssum[t] = 0.0f;
    }
    __syncthreads();

    #pragma unroll 1
    for (int blc = 0; blc < BC / BLC; ++blc) {
        const int bl0 = blc * BLC;

        ull s2[BLC];
        #pragma unroll
        for (int q = 0; q < BLC; ++q) s2[q] = 0ULL;

        // W for first i of this chunk (thread's 64B slice: bytes [64t, 64t+64))
        float4 n0, n1, n2, n3;
        {
            const float4* ws = ((const float4*)(Wg + (size_t)i0 * 4096)) + t * 4;
            n0 = ws[0]; n1 = ws[1]; n2 = ws[2]; n3 = ws[3];
        }
        ull wp[8];
        wp[0] = fpk(n0.x, n2.x); wp[1] = fpk(n0.y, n2.y);
        wp[2] = fpk(n0.z, n2.z); wp[3] = fpk(n0.w, n2.w);
        wp[4] = fpk(n1.x, n3.x); wp[5] = fpk(n1.y, n3.y);
        wp[6] = fpk(n1.z, n3.z); wp[7] = fpk(n1.w, n3.w);

        #pragma unroll 1
        for (int ic = 0; ic < IPER; ++ic) {
            // Prefetch next i's W
            if (ic + 1 < IPER) {
                const float4* ws = ((const float4*)(Wg + (size_t)(i0 + ic + 1) * 4096)) + t * 4;
                n0 = ws[0]; n1 = ws[1]; n2 = ws[2]; n3 = ws[3];
            }
            const int pb = ic & 1;

            // Zero the *other* ssum buffer (safe: last read 1 sync ago, next
            // write 2 syncs away). Idempotent on first iterations.
            if (ITER >= 1 && t < BLC) ssum[(pb ^ 1) * BLC + t] = 0.0f;

            ull u2s[BLC];
            #pragma unroll
            for (int q = 0; q < BLC; ++q) {
                const float4* xp = (const float4*)(xsh + (bl0 + q) * (IPER * 8) + ic * 8);
                float4 x0 = xp[0], x1 = xp[1];
                ull acc = (ITER == 0) ? s2[q] : 0ULL;
                acc = ffma2(wp[0], fdup(x0.x), acc);
                acc = ffma2(wp[1], fdup(x0.y), acc);
                acc = ffma2(wp[2], fdup(x0.z), acc);
                acc = ffma2(wp[3], fdup(x0.w), acc);
                acc = ffma2(wp[4], fdup(x1.x), acc);
                acc = ffma2(wp[5], fdup(x1.y), acc);
                acc = ffma2(wp[6], fdup(x1.z), acc);
                acc = ffma2(wp[7], fdup(x1.w), acc);
                if (ITER == 0) {
                    s2[q] = acc;                 // c = 1/32 folded at flush
                } else {
                    u2s[q] = acc;
                    // agreement partial over this thread's 2 j's
                    ull a2 = ffma2(acc, vsh[(size_t)(bl0 + q) * 256 + t], 0ULL);
                    float a = flo(a2) + fhi(a2);
                    // reduce over jp (8 lanes per o)
                    a += __shfl_xor_sync(0xffffffffu, a, 1);
                    a += __shfl_xor_sync(0xffffffffu, a, 2);
                    a += __shfl_xor_sync(0xffffffffu, a, 4);
                    float e = __expf(a);         // |a| small: no max-subtract
                    if (jp == 0) esh[(pb * BLC + q) * 32 + o] = e;
                    // sum over the warp's 4 o's, then one atomic per warp
                    float eo = e + __shfl_xor_sync(0xffffffffu, e, 8);
                    eo += __shfl_xor_sync(0xffffffffu, eo, 16);
                    if (lane == 0) atomicAdd(&ssum[pb * BLC + q], eo);
                }
            }

            if (ITER >= 1) {
                __syncthreads();
                #pragma unroll
                for (int q = 0; q < BLC; ++q) {
                    float ss = ssum[pb * BLC + q];
                    float e  = esh[(pb * BLC + q) * 32 + o];
                    ull  c2  = fdup(__fdividef(e, ss));
                    s2[q] = ffma2(c2, u2s[q], s2[q]);
                }
                __syncthreads();
            }

            // rotate W
            if (ic + 1 < IPER) {
                wp[0] = fpk(n0.x, n2.x); wp[1] = fpk(n0.y, n2.y);
                wp[2] = fpk(n0.z, n2.z); wp[3] = fpk(n0.w, n2.w);
                wp[4] = fpk(n1.x, n3.x); wp[5] = fpk(n1.y, n3.y);
                wp[6] = fpk(n1.z, n3.z); wp[7] = fpk(n1.w, n3.w);
            }
        }

        // Flush: thread owns (b, o, j=2jp, 2jp+1) -> one red.v2 per bl
        #pragma unroll
        for (int q = 0; q < BLC; ++q) {
            const int b = b_base + bl0 + q;
            float* dst = g_s + ((size_t)b * OC + o) * OD + 2 * jp;
            float f0 = flo(s2[q]), f1 = fhi(s2[q]);
            if (ITER == 0) { f0 *= (1.0f / 32.0f); f1 *= (1.0f / 32.0f); }
            red2(dst, f0, f1);
        }
    }
}

// ---------------------------------------------------------------------------
// Squash: reduce g_s over j, squash, emit v (accumulating v0+v1 for iter2's
// linearized logits) or the final output. Re-zeros g_s for the next pass /
// graph replay. grid 64 (b), block 512 (t = o*16 + j).
// ---------------------------------------------------------------------------
__global__ void squash_k(int iter, float* __restrict__ out) {
    const int b = blockIdx.x;
    const int t = threadIdx.x;
    const int idx = b * (OC * OD) + t;

    const float s = g_s[idx];
    float sq = s * s;
    #pragma unroll
    for (int d = 8; d >= 1; d >>= 1)
        sq += __shfl_xor_sync(0xffffffffu, sq, d);   // 16-lane groups share o

    const float scale = (sq / (1.0f + sq)) * rsqrtf(sq + 1e-9f);
    const float v = s * scale;

    if (iter == 0)      g_v[idx] = v;
    else if (iter == 1) g_v[idx] += v;     // veff = v0 + v1 (linearity)
    else                out[idx] = v;      // [b][o][j]

    g_s[idx] = 0.0f;   // clean for next pass / next replay
}

// ---------------------------------------------------------------------------
extern "C" void kernel_launch(void* const* d_in, const int* in_sizes, int n_in,
                              void* d_out, int out_size) {
    (void)n_in; (void)out_size;
    const float* x = (const float*)d_in[0];
    const float* W = (const float*)d_in[1];
    if (in_sizes[0] > in_sizes[1]) {  // defensive: x=1M elems, W=8.4M elems
        const float* tmp = x; x = W; W = tmp;
    }
    float* out = (float*)d_out;

    cudaFuncSetAttribute(caps_pass<0>, cudaFuncAttributeMaxDynamicSharedMemorySize, SMEM_BYTES);
    cudaFuncSetAttribute(caps_pass<1>, cudaFuncAttributeMaxDynamicSharedMemorySize, SMEM_BYTES);
    cudaFuncSetAttribute(caps_pass<2>, cudaFuncAttributeMaxDynamicSharedMemorySize, SMEM_BYTES);

    dim3 grid(GX, NB / BC);   // (128, 2)
    caps_pass<0><<<grid, 256, SMEM_BYTES>>>(x, W);
    squash_k<<<64, 512>>>(0, out);
    caps_pass<1><<<grid, 256, SMEM_BYTES>>>(x, W);
    squash_k<<<64, 512>>>(1, out);
    caps_pass<2><<<grid, 256, SMEM_BYTES>>>(x, W);
    squash_k<<<64, 512>>>(2, out);
}

// round 7
// speedup vs baseline: 1.0018x; 1.0018x over previous
#include <cuda_runtime.h>
#include <cstdint>
#include <cstddef>

// CapsuleLayer dynamic routing — j-distributed mapping, W-in-registers.
// B=64, IN_CAPS=2048, IN_DIM=8, OUT_CAPS=32, OUT_DIM=16, 3 routing iters.
// Linearity trick: iter2 logits = u.(v0+v1) -> no b_ij matrix needed.

#define NB   64
#define ICAP 2048
#define OC   32
#define OD   16
#define IPER 16
#define GX   (ICAP / IPER)   // 128
#define BC   32              // batches per CTA
#define BLC  16              // batch rows per register chunk (2 chunks)

typedef unsigned long long ull;

__device__ float g_s[NB * OC * OD];   // [b][o][j] accumulators (zeroed by squash)
__device__ float g_v[NB * OC * OD];   // [b][o][j]; iter2 reads v0+v1 here

// ---- f32x2 helpers -------------------------------------------------------
__device__ __forceinline__ ull ffma2(ull a, ull b, ull c) {
    ull d;
    asm("fma.rn.f32x2 %0, %1, %2, %3;" : "=l"(d) : "l"(a), "l"(b), "l"(c));
    return d;
}
__device__ __forceinline__ ull fdup(float x) {
    ull d;
    asm("mov.b64 %0, {%1, %1};" : "=l"(d) : "f"(x));
    return d;
}
__device__ __forceinline__ ull fpk(float lo, float hi) {
    ull d;
    asm("mov.b64 %0, {%1, %2};" : "=l"(d) : "f"(lo), "f"(hi));
    return d;
}
__device__ __forceinline__ float flo(ull v) { return __uint_as_float((unsigned)v); }
__device__ __forceinline__ float fhi(ull v) { return __uint_as_float((unsigned)(v >> 32)); }

__device__ __forceinline__ void red2(float* p, float a, float b) {
    asm volatile("red.global.add.v2.f32 [%0], {%1, %2};"
                 :: "l"(p), "f"(a), "f"(b) : "memory");
}

// SMEM layout:
//   vsh : [BC][256] ull  = 65536 B   (v[b][o][jp] pairs; index within b == t)
//   xsh : [BC][IPER][8] f = 16384 B
//   esh : [2][BLC][32] f  =  4096 B  (double-buffered exp values)
//   ssum: [2][BLC] f      =   128 B  (double-buffered exp-sums)
#define VSH_ULLS (BC * 256)
#define XSH_F    (BC * IPER * 8)
#define SMEM_BYTES (VSH_ULLS * 8 + XSH_F * 4 + 2 * BLC * 32 * 4 + 2 * BLC * 4)

template <int ITER>
__global__ __launch_bounds__(256, 2)
void caps_pass(const float* __restrict__ xg, const float* __restrict__ Wg) {
    extern __shared__ ull smem_u[];
    ull*   vsh  = smem_u;
    float* xsh  = (float*)(smem_u + VSH_ULLS);
    float* esh  = xsh + XSH_F;
    float* ssum = esh + 2 * BLC * 32;

    const int t    = threadIdx.x;
    const int lane = t & 31;
    const int o    = t >> 3;       // output capsule
    const int jp   = t & 7;        // j-pair: j = {2jp, 2jp+1}
    const int b_base = blockIdx.y * BC;
    const int i0     = blockIdx.x * IPER;

    // Stage x: per bl row, IPER*8 = 128 contiguous floats
    {
        const int bl = t >> 3, c8 = t & 7;
        const float4* src = (const float4*)(xg + (size_t)(b_base + bl) * (ICAP * 8) + i0 * 8);
        float4* dst = (float4*)(xsh + bl * (IPER * 8));
        #pragma unroll
        for (int c = 0; c < 4; ++c) dst[c8 * 4 + c] = src[c8 * 4 + c];
    }
    if (ITER >= 1) {
        const ull* vg = ((const ull*)g_v) + (size_t)b_base * 256;
        #pragma unroll
        for (int k = 0; k < 32; ++k) vsh[t + k * 256] = vg[t + k * 256];
        if (t < 2 * BLC) ssum[t] = 0.0f;
    }
    __syncthreads();

    #pragma unroll 1
    for (int blc = 0; blc < BC / BLC; ++blc) {
        const int bl0 = blc * BLC;

        ull s2[BLC];
        #pragma unroll
        for (int q = 0; q < BLC; ++q) s2[q] = 0ULL;

        // W for first i of this chunk (thread's 64B slice: bytes [64t, 64t+64))
        float4 n0, n1, n2, n3;
        {
            const float4* ws = ((const float4*)(Wg + (size_t)i0 * 4096)) + t * 4;
            n0 = ws[0]; n1 = ws[1]; n2 = ws[2]; n3 = ws[3];
        }
        ull wp[8];
        wp[0] = fpk(n0.x, n2.x); wp[1] = fpk(n0.y, n2.y);
        wp[2] = fpk(n0.z, n2.z); wp[3] = fpk(n0.w, n2.w);
        wp[4] = fpk(n1.x, n3.x); wp[5] = fpk(n1.y, n3.y);
        wp[6] = fpk(n1.z, n3.z); wp[7] = fpk(n1.w, n3.w);

        #pragma unroll 1
        for (int ic = 0; ic < IPER; ++ic) {
            // Prefetch next i's W
            if (ic + 1 < IPER) {
                const float4* ws = ((const float4*)(Wg + (size_t)(i0 + ic + 1) * 4096)) + t * 4;
                n0 = ws[0]; n1 = ws[1]; n2 = ws[2]; n3 = ws[3];
            }
            const int pb = ic & 1;

            // Zero the *other* ssum buffer (safe: last read 1 sync ago, next
            // write 2 syncs away). Idempotent on first iterations.
            if (ITER >= 1 && t < BLC) ssum[(pb ^ 1) * BLC + t] = 0.0f;

            ull u2s[BLC];
            #pragma unroll
            for (int q = 0; q < BLC; ++q) {
                const float4* xp = (const float4*)(xsh + (bl0 + q) * (IPER * 8) + ic * 8);
                float4 x0 = xp[0], x1 = xp[1];
                ull acc = (ITER == 0) ? s2[q] : 0ULL;
                acc = ffma2(wp[0], fdup(x0.x), acc);
                acc = ffma2(wp[1], fdup(x0.y), acc);
                acc = ffma2(wp[2], fdup(x0.z), acc);
                acc = ffma2(wp[3], fdup(x0.w), acc);
                acc = ffma2(wp[4], fdup(x1.x), acc);
                acc = ffma2(wp[5], fdup(x1.y), acc);
                acc = ffma2(wp[6], fdup(x1.z), acc);
                acc = ffma2(wp[7], fdup(x1.w), acc);
                if (ITER == 0) {
                    s2[q] = acc;                 // c = 1/32 folded at flush
                } else {
                    u2s[q] = acc;
                    // agreement partial over this thread's 2 j's
                    ull a2 = ffma2(acc, vsh[(size_t)(bl0 + q) * 256 + t], 0ULL);
                    float a = flo(a2) + fhi(a2);
                    // reduce over jp (8 lanes per o)
                    a += __shfl_xor_sync(0xffffffffu, a, 1);
                    a += __shfl_xor_sync(0xffffffffu, a, 2);
                    a += __shfl_xor_sync(0xffffffffu, a, 4);
                    float e = __expf(a);         // |a| small: no max-subtract
                    if (jp == 0) esh[(pb * BLC + q) * 32 + o] = e;
                    // sum over the warp's 4 o's, then one atomic per warp
                    float eo = e + __shfl_xor_sync(0xffffffffu, e, 8);
                    eo += __shfl_xor_sync(0xffffffffu, eo, 16);
                    if (lane == 0) atomicAdd(&ssum[pb * BLC + q], eo);
                }
            }

            if (ITER >= 1) {
                __syncthreads();
                #pragma unroll
                for (int q = 0; q < BLC; ++q) {
                    float ss = ssum[pb * BLC + q];
                    float e  = esh[(pb * BLC + q) * 32 + o];
                    ull  c2  = fdup(__fdividef(e, ss));
                    s2[q] = ffma2(c2, u2s[q], s2[q]);
                }
                __syncthreads();
            }

            // rotate W
            if (ic + 1 < IPER) {
                wp[0] = fpk(n0.x, n2.x); wp[1] = fpk(n0.y, n2.y);
                wp[2] = fpk(n0.z, n2.z); wp[3] = fpk(n0.w, n2.w);
                wp[4] = fpk(n1.x, n3.x); wp[5] = fpk(n1.y, n3.y);
                wp[6] = fpk(n1.z, n3.z); wp[7] = fpk(n1.w, n3.w);
            }
        }

        // Flush: thread owns (b, o, j=2jp, 2jp+1) -> one red.v2 per bl
        #pragma unroll
        for (int q = 0; q < BLC; ++q) {
            const int b = b_base + bl0 + q;
            float* dst = g_s + ((size_t)b * OC + o) * OD + 2 * jp;
            float f0 = flo(s2[q]), f1 = fhi(s2[q]);
            if (ITER == 0) { f0 *= (1.0f / 32.0f); f1 *= (1.0f / 32.0f); }
            red2(dst, f0, f1);
        }
    }
}

// ---------------------------------------------------------------------------
// Squash: reduce g_s over j, squash, emit v (accumulating v0+v1 for iter2's
// linearized logits) or the final output. Re-zeros g_s for the next pass /
// graph replay. grid 64 (b), block 512 (t = o*16 + j).
// ---------------------------------------------------------------------------
__global__ void squash_k(int iter, float* __restrict__ out) {
    const int b = blockIdx.x;
    const int t = threadIdx.x;
    const int idx = b * (OC * OD) + t;

    const float s = g_s[idx];
    float sq = s * s;
    #pragma unroll
    for (int d = 8; d >= 1; d >>= 1)
        sq += __shfl_xor_sync(0xffffffffu, sq, d);   // 16-lane groups share o

    const float scale = (sq / (1.0f + sq)) * rsqrtf(sq + 1e-9f);
    const float v = s * scale;

    if (iter == 0)      g_v[idx] = v;
    else if (iter == 1) g_v[idx] += v;     // veff = v0 + v1 (linearity)
    else                out[idx] = v;      // [b][o][j]

    g_s[idx] = 0.0f;   // clean for next pass / next replay
}

// ---------------------------------------------------------------------------
extern "C" void kernel_launch(void* const* d_in, const int* in_sizes, int n_in,
                              void* d_out, int out_size) {
    (void)n_in; (void)out_size;
    const float* x = (const float*)d_in[0];
    const float* W = (const float*)d_in[1];
    if (in_sizes[0] > in_sizes[1]) {  // defensive: x=1M elems, W=8.4M elems
        const float* tmp = x; x = W; W = tmp;
    }
    float* out = (float*)d_out;

    cudaFuncSetAttribute(caps_pass<0>, cudaFuncAttributeMaxDynamicSharedMemorySize, SMEM_BYTES);
    cudaFuncSetAttribute(caps_pass<1>, cudaFuncAttributeMaxDynamicSharedMemorySize, SMEM_BYTES);
    cudaFuncSetAttribute(caps_pass<2>, cudaFuncAttributeMaxDynamicSharedMemorySize, SMEM_BYTES);

    dim3 grid(GX, NB / BC);   // (128, 2)
    caps_pass<0><<<grid, 256, SMEM_BYTES>>>(x, W);
    squash_k<<<64, 512>>>(0, out);
    caps_pass<1><<<grid, 256, SMEM_BYTES>>>(x, W);
    squash_k<<<64, 512>>>(1, out);
    caps_pass<2><<<grid, 256, SMEM_BYTES>>>(x, W);
    squash_k<<<64, 512>>>(2, out);
}